// round 2
// baseline (speedup 1.0000x reference)
#include <cuda_runtime.h>

// ---------------- problem constants ----------------
#define O   130          // output spatial extent per axis
#define P   (O*O)        // 16900, one plane
#define O3  2197000      // 130^3
#define CH  12
// input is 128^3

// ---------------- scratch (device globals: no allocs allowed) ----------------
__device__ float g_buf[(size_t)CH * O3];   // WH-boxed diff^2 sums, [c][z][y][w]
__device__ float g_mv[O3];                 // per-voxel mind_var
__device__ float g_partial[4 * 67];        // per-block partial sums of mind_var
__device__ float g_clip[2];                // {lo, hi}

// shift offsets (oz, oy, ow) for the 6 one-hot dilated stencils, in padded coords
__constant__ int c_offs[6][3] = {
    {-1, 1, 1},   // s0: z-minus
    { 1, 1,-1},   // s1: w-minus
    { 1,-1, 1},   // s2: y-minus
    { 1, 1, 3},   // s3: w-plus
    { 3, 1, 1},   // s4: z-plus
    { 1, 3, 1}    // s5: y-plus
};
// channel -> (shift_i, shift_j), in the reference's mask order
__constant__ int c_pairs[CH][2] = {
    {1,0},{2,0},{2,1},{3,0},{3,2},{4,1},{4,2},{4,3},{5,0},{5,1},{5,3},{5,4}
};

// sample x at padded coords (jz,jy,jw): zero outside [0,131], edge-clamped inside
__device__ __forceinline__ float samp(const float* __restrict__ x,
                                      int jz, int jy, int jw) {
    bool ok = (jz >= 0) & (jz <= 131) & (jy >= 0) & (jy <= 131) & (jw >= 0) & (jw <= 131);
    int xz = min(max(jz - 2, 0), 127);
    int xy = min(max(jy - 2, 0), 127);
    int xw = min(max(jw - 2, 0), 127);
    float v = 0.0f;
    if (ok) v = __ldg(&x[((xz << 7) + xy) * 128 + xw]);
    return v;
}

// ---------------- K1: diff^2 -> W-box -> H-box, one (c, z, y-strip) per block ----
#define STRIP 32
#define SROWS 36   // STRIP + 4 halo rows

__global__ __launch_bounds__(256) void k1_kernel(const float* __restrict__ x) {
    __shared__ float s_d2[SROWS][132];
    __shared__ float s_rs[SROWS][132];

    const int c  = blockIdx.z;
    const int z  = blockIdx.y;
    const int y0 = blockIdx.x * STRIP;
    const int sa = c_pairs[c][0], sb = c_pairs[c][1];
    const int oza = c_offs[sa][0], oya = c_offs[sa][1], owa = c_offs[sa][2];
    const int ozb = c_offs[sb][0], oyb = c_offs[sb][1], owb = c_offs[sb][2];
    const int tid = threadIdx.x;

    // step A: diff^2 for rows clamp(y0-2 .. y0+33)
    for (int idx = tid; idx < SROWS * O; idx += 256) {
        int ly = idx / O;
        int w  = idx - ly * O;
        int ay = min(max(y0 - 2 + ly, 0), O - 1);
        float va = samp(x, z + oza, ay + oya, w + owa);
        float vb = samp(x, z + ozb, ay + oyb, w + owb);
        float d  = va - vb;
        s_d2[ly][w] = d * d;
    }
    __syncthreads();

    // step B: clamped box sum along W
    for (int idx = tid; idx < SROWS * O; idx += 256) {
        int ly = idx / O;
        int w  = idx - ly * O;
        float s = 0.0f;
        #pragma unroll
        for (int k = 0; k < 5; k++) {
            int ww = min(max(w + k - 2, 0), O - 1);
            s += s_d2[ly][ww];
        }
        s_rs[ly][w] = s;
    }
    __syncthreads();

    // step C: clamped box sum along H, write plane strip
    const int nrows = min(STRIP, O - y0);
    for (int idx = tid; idx < nrows * O; idx += 256) {
        int ry = idx / O;
        int w  = idx - ry * O;
        float s = s_rs[ry][w] + s_rs[ry+1][w] + s_rs[ry+2][w]
                + s_rs[ry+3][w] + s_rs[ry+4][w];
        g_buf[((size_t)(c * O + z) * O + (y0 + ry)) * O + w] = s;
    }
}

// ---------------- K2: z-box (running window) + channel min/mean ----------------
#define ZCH  4
#define ZLEN 33
#define PBLK 67   // ceil(16900/256)

__global__ __launch_bounds__(256) void k2_kernel(float* __restrict__ mind) {
    const int tid = threadIdx.x;
    const int v   = blockIdx.x * 256 + tid;     // voxel index in a plane
    const int z0  = blockIdx.y * ZLEN;
    const int z1  = min(z0 + ZLEN, O);
    float acc = 0.0f;

    if (v < P) {
        float sums[CH], w0[CH], w1[CH], w2[CH], w3[CH];
        #pragma unroll
        for (int c = 0; c < CH; c++) sums[c] = 0.0f;

        // prefill window with planes clamp(z0-2 .. z0+1)
        #pragma unroll
        for (int q = 0; q < 4; q++) {
            int pz = min(max(z0 - 2 + q, 0), O - 1);
            #pragma unroll
            for (int c = 0; c < CH; c++) {
                float t = g_buf[((size_t)c * O + pz) * P + v];
                sums[c] += t;
                if (q == 0) w0[c] = t;
                else if (q == 1) w1[c] = t;
                else if (q == 2) w2[c] = t;
                else w3[c] = t;
            }
        }

        for (int z = z0; z < z1; z++) {
            int pz = min(z + 2, O - 1);
            float nv[CH];
            #pragma unroll
            for (int c = 0; c < CH; c++) {
                nv[c] = g_buf[((size_t)c * O + pz) * P + v];
                sums[c] += nv[c];
            }
            // per-voxel channel min and total
            float mn = sums[0], tot = sums[0];
            #pragma unroll
            for (int c = 1; c < CH; c++) { mn = fminf(mn, sums[c]); tot += sums[c]; }

            #pragma unroll
            for (int c = 0; c < CH; c++)
                mind[((size_t)c * O + z) * P + v] = (sums[c] - mn) * (1.0f / 125.0f);

            float mvv = (tot * (1.0f / 12.0f) - mn) * (1.0f / 125.0f);
            g_mv[z * P + v] = mvv;
            acc += mvv;

            // evict oldest (z-2), shift window
            #pragma unroll
            for (int c = 0; c < CH; c++) {
                sums[c] -= w0[c];
                w0[c] = w1[c]; w1[c] = w2[c]; w2[c] = w3[c]; w3[c] = nv[c];
            }
        }
    }

    // deterministic block reduction of mind_var partial sum
    __shared__ float red[256];
    red[tid] = acc;
    __syncthreads();
    for (int s = 128; s > 0; s >>= 1) {
        if (tid < s) red[tid] += red[tid + s];
        __syncthreads();
    }
    if (tid == 0) g_partial[blockIdx.y * PBLK + blockIdx.x] = red[0];
}

// ---------------- K2b: deterministic final reduction -> clip bounds ------------
__global__ void k2b_kernel() {
    __shared__ float red[256];
    const int tid = threadIdx.x;
    float a = 0.0f;
    for (int i = tid; i < ZCH * PBLK; i += 256) a += g_partial[i];
    red[tid] = a;
    __syncthreads();
    for (int s = 128; s > 0; s >>= 1) {
        if (tid < s) red[tid] += red[tid + s];
        __syncthreads();
    }
    if (tid == 0) {
        float mean = red[0] / (float)O3;
        g_clip[0] = mean * 0.001f;
        g_clip[1] = mean * 1000.0f;
    }
}

// ---------------- K3: in-place exp(-mind / clipped var) ------------------------
__global__ __launch_bounds__(256) void k3_kernel(float* __restrict__ out) {
    const int v = blockIdx.x * 256 + threadIdx.x;
    if (v >= O3) return;
    float lo = g_clip[0], hi = g_clip[1];
    float m  = fminf(fmaxf(g_mv[v], lo), hi);
    float inv = 1.0f / m;
    #pragma unroll
    for (int c = 0; c < CH; c++) {
        size_t i = (size_t)c * O3 + v;
        out[i] = __expf(-out[i] * inv);
    }
}

// ---------------- launch ----------------
extern "C" void kernel_launch(void* const* d_in, const int* in_sizes, int n_in,
                              void* d_out, int out_size) {
    const float* x = (const float*)d_in[0];
    float* out = (float*)d_out;

    dim3 g1(5, O, CH);           // y-strips, z, channel
    k1_kernel<<<g1, 256>>>(x);

    dim3 g2(PBLK, ZCH);
    k2_kernel<<<g2, 256>>>(out);

    k2b_kernel<<<1, 256>>>();

    k3_kernel<<<(O3 + 255) / 256, 256>>>(out);
}

// round 3
// speedup vs baseline: 1.2374x; 1.2374x over previous
#include <cuda_runtime.h>

// ---------------- problem constants ----------------
#define O   130          // output spatial extent per axis
#define P   (O*O)        // 16900, one plane
#define O3  2197000      // 130^3
#define CH  12
// input x is 128^3

// ---------------- scratch (device globals: no allocs allowed) ----------------
__device__ float g_buf[(size_t)CH * O3];   // WH-boxed diff^2 sums, [c][z][y][w]
__device__ float g_partial[10 * 67];       // per-block partial sums of mind_var
__device__ float g_clip[2];                // {lo, hi}

// shift offsets (oz, oy, ow) for the 6 one-hot dilated stencils, in padded coords
__constant__ int c_offs[6][3] = {
    {-1, 1, 1},   // s0: z-minus
    { 1, 1,-1},   // s1: w-minus
    { 1,-1, 1},   // s2: y-minus
    { 1, 1, 3},   // s3: w-plus
    { 3, 1, 1},   // s4: z-plus
    { 1, 3, 1}    // s5: y-plus
};
// channel -> (shift_i, shift_j), in the reference's mask order
__constant__ int c_pairs[CH][2] = {
    {1,0},{2,0},{2,1},{3,0},{3,2},{4,1},{4,2},{4,3},{5,0},{5,1},{5,3},{5,4}
};

// ---------------- K1: 6 shift planes -> 12 diff^2 -> W-box -> H-box ------------
// block = (y-strip of 8, z). smem: 6 shift planes (12 halo rows) + one boxed-row buf
#define STRIP 8
#define SR    12           // STRIP + 4 halo rows
#define NSTRIP 17          // ceil(130/8)

__global__ __launch_bounds__(256) void k1_kernel(const float* __restrict__ x) {
    __shared__ float s_v[6][SR][O];    // 6 shifted-value planes      (37.4 KB)
    __shared__ float s_rs[SR][O];      // W-boxed diff^2 rows (per ch) (6.2 KB)

    const int z   = blockIdx.y;
    const int y0  = blockIdx.x * STRIP;
    const int tid = threadIdx.x;

    // ---- step A: sample 6 shifted planes for rows ay = clamp(y0-2+r) ----
    #pragma unroll
    for (int s = 0; s < 6; s++) {
        const int oz = c_offs[s][0], oy = c_offs[s][1], ow = c_offs[s][2];
        const int jz = z + oz;
        const bool zok = (jz >= 0) && (jz <= 131);
        const int xz = min(max(jz - 2, 0), 127);
        const float* xp = x + (size_t)xz * 16384;   // 128*128
        for (int idx = tid; idx < SR * O; idx += 256) {
            int r = idx / O;
            int w = idx - r * O;
            int ay = min(max(y0 - 2 + r, 0), O - 1);
            int jy = ay + oy;
            int jw = w + ow;
            bool ok = zok && (jy >= 0) && (jy <= 131) && (jw >= 0) && (jw <= 131);
            int xy = min(max(jy - 2, 0), 127);
            int xw = min(max(jw - 2, 0), 127);
            float v = 0.0f;
            if (ok) v = __ldg(&xp[(xy << 7) + xw]);
            s_v[s][r][w] = v;
        }
    }
    __syncthreads();

    const int nrows = min(STRIP, O - y0);
    const int npair = (nrows + 1) >> 1;

    for (int c = 0; c < CH; c++) {
        const int si = c_pairs[c][0], sj = c_pairs[c][1];
        const float* vi = &s_v[si][0][0];
        const float* vj = &s_v[sj][0][0];

        // ---- step B: clamped 5-tap box along W, two outputs per item ----
        for (int idx = tid; idx < SR * 65; idx += 256) {
            int r  = idx / 65;
            int wp = idx - r * 65;
            int w0 = wp << 1;
            const float* vir = vi + r * O;
            const float* vjr = vj + r * O;
            float t[6];
            #pragma unroll
            for (int k = 0; k < 6; k++) {
                int ww = min(max(w0 - 2 + k, 0), O - 1);
                float d = vir[ww] - vjr[ww];
                t[k] = d * d;
            }
            s_rs[r][w0]     = t[0] + t[1] + t[2] + t[3] + t[4];
            s_rs[r][w0 + 1] = t[1] + t[2] + t[3] + t[4] + t[5];
        }
        __syncthreads();

        // ---- step C: 5-tap box along H (rows), two outputs per item ----
        float* gb = &g_buf[((size_t)(c * O + z) * O + y0) * O];
        for (int idx = tid; idx < npair * O; idx += 256) {
            int rp = idx / O;
            int w  = idx - rp * O;
            int ry = rp << 1;
            float a0 = s_rs[ry][w], a1 = s_rs[ry+1][w], a2 = s_rs[ry+2][w],
                  a3 = s_rs[ry+3][w], a4 = s_rs[ry+4][w];
            float o0 = a0 + a1 + a2 + a3 + a4;
            gb[ry * O + w] = o0;
            if (ry + 1 < nrows)
                gb[(ry + 1) * O + w] = o0 - a0 + s_rs[ry+5][w];
        }
        __syncthreads();   // protect s_rs before next channel rewrites it
    }
}

// ---------------- K2: z-box (running window) + channel min, write mind ---------
#define ZCH  10
#define ZLEN 13
#define PBLK 67   // ceil(16900/256)

__global__ __launch_bounds__(256) void k2_kernel(float* __restrict__ mind) {
    const int tid = threadIdx.x;
    const int v   = blockIdx.x * 256 + tid;     // voxel index in a plane
    const int z0  = blockIdx.y * ZLEN;
    const int z1  = min(z0 + ZLEN, O);
    float acc = 0.0f;

    if (v < P) {
        float sums[CH], w0[CH], w1[CH], w2[CH], w3[CH];
        #pragma unroll
        for (int c = 0; c < CH; c++) sums[c] = 0.0f;

        #pragma unroll
        for (int q = 0; q < 4; q++) {
            int pz = min(max(z0 - 2 + q, 0), O - 1);
            #pragma unroll
            for (int c = 0; c < CH; c++) {
                float t = g_buf[((size_t)c * O + pz) * P + v];
                sums[c] += t;
                if (q == 0) w0[c] = t;
                else if (q == 1) w1[c] = t;
                else if (q == 2) w2[c] = t;
                else w3[c] = t;
            }
        }

        for (int z = z0; z < z1; z++) {
            int pz = min(z + 2, O - 1);
            float nv[CH];
            #pragma unroll
            for (int c = 0; c < CH; c++) {
                nv[c] = g_buf[((size_t)c * O + pz) * P + v];
                sums[c] += nv[c];
            }
            float mn = sums[0], tot = sums[0];
            #pragma unroll
            for (int c = 1; c < CH; c++) { mn = fminf(mn, sums[c]); tot += sums[c]; }

            #pragma unroll
            for (int c = 0; c < CH; c++)
                mind[((size_t)c * O + z) * P + v] = (sums[c] - mn) * (1.0f / 125.0f);

            acc += (tot * (1.0f / 12.0f) - mn) * (1.0f / 125.0f);

            #pragma unroll
            for (int c = 0; c < CH; c++) {
                sums[c] -= w0[c];
                w0[c] = w1[c]; w1[c] = w2[c]; w2[c] = w3[c]; w3[c] = nv[c];
            }
        }
    }

    __shared__ float red[256];
    red[tid] = acc;
    __syncthreads();
    for (int s = 128; s > 0; s >>= 1) {
        if (tid < s) red[tid] += red[tid + s];
        __syncthreads();
    }
    if (tid == 0) g_partial[blockIdx.y * PBLK + blockIdx.x] = red[0];
}

// ---------------- K2b: deterministic final reduction -> clip bounds ------------
__global__ void k2b_kernel() {
    __shared__ float red[256];
    const int tid = threadIdx.x;
    float a = 0.0f;
    for (int i = tid; i < ZCH * PBLK; i += 256) a += g_partial[i];
    red[tid] = a;
    __syncthreads();
    for (int s = 128; s > 0; s >>= 1) {
        if (tid < s) red[tid] += red[tid + s];
        __syncthreads();
    }
    if (tid == 0) {
        float mean = red[0] / (float)O3;
        g_clip[0] = mean * 0.001f;
        g_clip[1] = mean * 1000.0f;
    }
}

// ---------------- K3: recompute var from channels, exp, float4-vectorized ------
#define Q4 (O3 / 4)    // 549250

__global__ __launch_bounds__(256) void k3_kernel(float* __restrict__ out) {
    const int v4 = blockIdx.x * 256 + threadIdx.x;
    if (v4 >= Q4) return;
    float4* o4 = (float4*)out;

    float4 m[CH];
    #pragma unroll
    for (int c = 0; c < CH; c++) m[c] = o4[(size_t)c * Q4 + v4];

    float sx = 0.f, sy = 0.f, sz = 0.f, sw = 0.f;
    #pragma unroll
    for (int c = 0; c < CH; c++) {
        sx += m[c].x; sy += m[c].y; sz += m[c].z; sw += m[c].w;
    }
    const float lo = g_clip[0], hi = g_clip[1];
    float ix = 1.0f / fminf(fmaxf(sx * (1.0f/12.0f), lo), hi);
    float iy = 1.0f / fminf(fmaxf(sy * (1.0f/12.0f), lo), hi);
    float iz = 1.0f / fminf(fmaxf(sz * (1.0f/12.0f), lo), hi);
    float iw = 1.0f / fminf(fmaxf(sw * (1.0f/12.0f), lo), hi);

    #pragma unroll
    for (int c = 0; c < CH; c++) {
        float4 r;
        r.x = __expf(-m[c].x * ix);
        r.y = __expf(-m[c].y * iy);
        r.z = __expf(-m[c].z * iz);
        r.w = __expf(-m[c].w * iw);
        o4[(size_t)c * Q4 + v4] = r;
    }
}

// ---------------- launch ----------------
extern "C" void kernel_launch(void* const* d_in, const int* in_sizes, int n_in,
                              void* d_out, int out_size) {
    const float* x = (const float*)d_in[0];
    float* out = (float*)d_out;

    dim3 g1(NSTRIP, O);
    k1_kernel<<<g1, 256>>>(x);

    dim3 g2(PBLK, ZCH);
    k2_kernel<<<g2, 256>>>(out);

    k2b_kernel<<<1, 256>>>();

    k3_kernel<<<(Q4 + 255) / 256, 256>>>(out);
}